// round 7
// baseline (speedup 1.0000x reference)
#include <cuda_runtime.h>
#include <math.h>
#include <stdint.h>

#define NN 100000
#define EE 6400000
#define RR 90

// ---------------- static device scratch (allocation-free rule) ----------------
__device__ int    g_cnt[(size_t)NN * RR];   // per-(dst,rel) edge counts (36 MB)
__device__ int    g_deg[NN];                // per-dst degree
__device__ int2   g_range[NN];              // (beg, end) per node in g_sorted
__device__ int    g_cursor[NN];             // scatter cursors
__device__ int    g_total;                  // running offset counter
__device__ int    g_sorted[EE];             // dst-grouped packed (src<<7 | rel)
__device__ float4 g_x4[NN];                 // x padded to 4
__device__ float4 g_h1[(size_t)NN * 2];     // h1, stride 8 floats (6 used + 2 pad)
__device__ float4 g_h2[NN];                 // h2, stride 4 floats (3 used + 1 pad)
__device__ float  g_pool[8];

// ---------------- zero counts/deg/pool + pad x ----------------
__global__ void zero_pad(const float* __restrict__ x) {
    int idx = blockIdx.x * blockDim.x + threadIdx.x;
    int stride = gridDim.x * blockDim.x;
    int4* c = (int4*)g_cnt;
    const int n4 = (NN * RR) / 4;
    for (int i = idx; i < n4; i += stride) c[i] = make_int4(0, 0, 0, 0);
    for (int i = idx; i < NN; i += stride) {
        g_deg[i] = 0;
        g_x4[i] = make_float4(x[i * 3], x[i * 3 + 1], x[i * 3 + 2], 0.f);
    }
    if (idx < 8) g_pool[idx] = 0.f;
    if (idx == 0) g_total = 0;
}

// ---------------- count pass: cnt[dst*R+et]++ and deg[dst]++ ----------------
__global__ void count_deg(const int* __restrict__ dst, const int* __restrict__ et) {
    const int4* d4 = (const int4*)dst;
    const int4* e4 = (const int4*)et;
    const int n4 = EE / 4;
    int stride = gridDim.x * blockDim.x;
    for (int i = blockIdx.x * blockDim.x + threadIdx.x; i < n4; i += stride) {
        int4 d = d4[i];
        int4 e = e4[i];
        atomicAdd(&g_cnt[d.x * RR + e.x], 1);
        atomicAdd(&g_cnt[d.y * RR + e.y], 1);
        atomicAdd(&g_cnt[d.z * RR + e.z], 1);
        atomicAdd(&g_cnt[d.w * RR + e.w], 1);
        atomicAdd(&g_deg[d.x], 1);
        atomicAdd(&g_deg[d.y], 1);
        atomicAdd(&g_deg[d.z], 1);
        atomicAdd(&g_deg[d.w], 1);
    }
}

// ---------------- range assignment: warp-aggregated atomic (no scan needed) ----------------
// Node order inside g_sorted is irrelevant; any disjoint range assignment works.
__global__ void offsets_k() {
    int i = blockIdx.x * blockDim.x + threadIdx.x;
    if (i >= NN) return;               // NN % 32 == 0 -> whole warps exit together
    int lane = threadIdx.x & 31;
    int d = g_deg[i];
    int x = d;
#pragma unroll
    for (int o = 1; o < 32; o <<= 1) {
        int y = __shfl_up_sync(0xffffffffu, x, o);
        if (lane >= o) x += y;
    }
    int warptot = __shfl_sync(0xffffffffu, x, 31);
    int base = 0;
    if (lane == 31) base = atomicAdd(&g_total, warptot);
    base = __shfl_sync(0xffffffffu, base, 31);
    int beg = base + x - d;
    g_range[i] = make_int2(beg, beg + d);
    g_cursor[i] = beg;
}

// ---------------- counting-sort scatter: g_sorted[pos] = src<<7 | rel ----------------
__global__ void scatter_k(const int* __restrict__ src, const int* __restrict__ dst,
                          const int* __restrict__ et) {
    const int4* s4 = (const int4*)src;
    const int4* d4 = (const int4*)dst;
    const int4* e4 = (const int4*)et;
    const int n4 = EE / 4;
    int stride = gridDim.x * blockDim.x;
    for (int i = blockIdx.x * blockDim.x + threadIdx.x; i < n4; i += stride) {
        int4 s = s4[i];
        int4 d = d4[i];
        int4 t = e4[i];
        int p0 = atomicAdd(&g_cursor[d.x], 1);
        int p1 = atomicAdd(&g_cursor[d.y], 1);
        int p2 = atomicAdd(&g_cursor[d.z], 1);
        int p3 = atomicAdd(&g_cursor[d.w], 1);
        g_sorted[p0] = (s.x << 7) | t.x;
        g_sorted[p1] = (s.y << 7) | t.y;
        g_sorted[p2] = (s.z << 7) | t.z;
        g_sorted[p3] = (s.w << 7) | t.w;
    }
}

// ---------------- layer 1: mean aggr (3 -> 6) + root + relu, warp per node ----------------
__global__ void __launch_bounds__(256) layer1_k(const float* __restrict__ W,
                                                const float* __restrict__ root,
                                                const float* __restrict__ bias) {
    __shared__ float sW[RR * 6];
    __shared__ float sR[18], sB[6];
    for (int i = threadIdx.x; i < RR * 6; i += blockDim.x) sW[i] = W[i];
    if (threadIdx.x < 18) sR[threadIdx.x] = root[threadIdx.x];
    if (threadIdx.x < 6) sB[threadIdx.x] = bias[threadIdx.x];
    __syncthreads();
    int gw = (blockIdx.x * blockDim.x + threadIdx.x) >> 5;
    if (gw >= NN) return;
    int lane = threadIdx.x & 31;
    int2 rg = g_range[gw];
    const int* cntRow = g_cnt + (size_t)gw * RR;
    float a0 = 0, a1 = 0, a2 = 0, a3 = 0, a4 = 0, a5 = 0;
    int e = rg.x + lane;
    for (; e + 32 < rg.y; e += 64) {
        int p0 = g_sorted[e];
        int p1 = g_sorted[e + 32];
        float4 x0 = __ldg(&g_x4[p0 >> 7]);
        float4 x1 = __ldg(&g_x4[p1 >> 7]);
        float iv0 = __fdividef(1.f, (float)cntRow[p0 & 127]);
        float iv1 = __fdividef(1.f, (float)cntRow[p1 & 127]);
        const float* w0 = sW + (p0 & 127) * 6;
        const float* w1 = sW + (p1 & 127) * 6;
        float t0 = x0.x * iv0, t1 = x0.y * iv0, t2 = x0.z * iv0;
        a0 += t0 * w0[0]; a1 += t0 * w0[1];
        a2 += t1 * w0[2]; a3 += t1 * w0[3];
        a4 += t2 * w0[4]; a5 += t2 * w0[5];
        float u0 = x1.x * iv1, u1 = x1.y * iv1, u2 = x1.z * iv1;
        a0 += u0 * w1[0]; a1 += u0 * w1[1];
        a2 += u1 * w1[2]; a3 += u1 * w1[3];
        a4 += u2 * w1[4]; a5 += u2 * w1[5];
    }
    if (e < rg.y) {
        int p0 = g_sorted[e];
        float4 x0 = __ldg(&g_x4[p0 >> 7]);
        float iv0 = __fdividef(1.f, (float)cntRow[p0 & 127]);
        const float* w0 = sW + (p0 & 127) * 6;
        float t0 = x0.x * iv0, t1 = x0.y * iv0, t2 = x0.z * iv0;
        a0 += t0 * w0[0]; a1 += t0 * w0[1];
        a2 += t1 * w0[2]; a3 += t1 * w0[3];
        a4 += t2 * w0[4]; a5 += t2 * w0[5];
    }
#pragma unroll
    for (int o = 16; o; o >>= 1) {
        a0 += __shfl_down_sync(0xffffffffu, a0, o);
        a1 += __shfl_down_sync(0xffffffffu, a1, o);
        a2 += __shfl_down_sync(0xffffffffu, a2, o);
        a3 += __shfl_down_sync(0xffffffffu, a3, o);
        a4 += __shfl_down_sync(0xffffffffu, a4, o);
        a5 += __shfl_down_sync(0xffffffffu, a5, o);
    }
    if (lane == 0) {
        float4 xv = g_x4[gw];
        float h[6] = {a0, a1, a2, a3, a4, a5};
#pragma unroll
        for (int j = 0; j < 6; j++) {
            float v = h[j] + xv.x * sR[j] + xv.y * sR[6 + j] + xv.z * sR[12 + j] + sB[j];
            h[j] = v > 0.f ? v : 0.f;
        }
        g_h1[(size_t)gw * 2]     = make_float4(h[0], h[1], h[2], h[3]);
        g_h1[(size_t)gw * 2 + 1] = make_float4(h[4], h[5], 0.f, 0.f);
    }
}

// ---------------- layer 2: add aggr (6 -> 3) + root + relu, warp per node ----------------
__global__ void __launch_bounds__(256) layer2_k(const float* __restrict__ W,
                                                const float* __restrict__ root,
                                                const float* __restrict__ bias) {
    __shared__ float sW[RR * 6];
    __shared__ float sR[18], sB[3];
    for (int i = threadIdx.x; i < RR * 6; i += blockDim.x) sW[i] = W[i];
    if (threadIdx.x < 18) sR[threadIdx.x] = root[threadIdx.x];
    if (threadIdx.x < 3) sB[threadIdx.x] = bias[threadIdx.x];
    __syncthreads();
    int gw = (blockIdx.x * blockDim.x + threadIdx.x) >> 5;
    if (gw >= NN) return;
    int lane = threadIdx.x & 31;
    int2 rg = g_range[gw];
    float a0 = 0, a1 = 0, a2 = 0;
    int e = rg.x + lane;
    for (; e + 32 < rg.y; e += 64) {
        int p0 = g_sorted[e];
        int p1 = g_sorted[e + 32];
        int s0 = p0 >> 7, s1 = p1 >> 7;
        float4 ha0 = __ldg(&g_h1[(size_t)s0 * 2]);
        float4 hb0 = __ldg(&g_h1[(size_t)s0 * 2 + 1]);
        float4 ha1 = __ldg(&g_h1[(size_t)s1 * 2]);
        float4 hb1 = __ldg(&g_h1[(size_t)s1 * 2 + 1]);
        const float* w0 = sW + (p0 & 127) * 6;
        const float* w1 = sW + (p1 & 127) * 6;
        a0 += ha0.x * w0[0] + ha0.y * w0[1];
        a1 += ha0.z * w0[2] + ha0.w * w0[3];
        a2 += hb0.x * w0[4] + hb0.y * w0[5];
        a0 += ha1.x * w1[0] + ha1.y * w1[1];
        a1 += ha1.z * w1[2] + ha1.w * w1[3];
        a2 += hb1.x * w1[4] + hb1.y * w1[5];
    }
    if (e < rg.y) {
        int p0 = g_sorted[e];
        int s0 = p0 >> 7;
        float4 ha0 = __ldg(&g_h1[(size_t)s0 * 2]);
        float4 hb0 = __ldg(&g_h1[(size_t)s0 * 2 + 1]);
        const float* w0 = sW + (p0 & 127) * 6;
        a0 += ha0.x * w0[0] + ha0.y * w0[1];
        a1 += ha0.z * w0[2] + ha0.w * w0[3];
        a2 += hb0.x * w0[4] + hb0.y * w0[5];
    }
#pragma unroll
    for (int o = 16; o; o >>= 1) {
        a0 += __shfl_down_sync(0xffffffffu, a0, o);
        a1 += __shfl_down_sync(0xffffffffu, a1, o);
        a2 += __shfl_down_sync(0xffffffffu, a2, o);
    }
    if (lane == 0) {
        float4 ha = g_h1[(size_t)gw * 2];
        float4 hb = g_h1[(size_t)gw * 2 + 1];
        float hin[6] = {ha.x, ha.y, ha.z, ha.w, hb.x, hb.y};
        float h[3] = {a0, a1, a2};
#pragma unroll
        for (int j = 0; j < 3; j++) {
            float v = h[j] + sB[j];
#pragma unroll
            for (int k = 0; k < 6; k++) v += hin[k] * sR[k * 3 + j];
            h[j] = v > 0.f ? v : 0.f;
        }
        g_h2[gw] = make_float4(h[0], h[1], h[2], 0.f);
    }
}

// ---------------- layer 3: mean aggr (3 -> 6) + root + relu + mean pool ----------------
__global__ void __launch_bounds__(256) layer3_k(const float* __restrict__ W,
                                                const float* __restrict__ root,
                                                const float* __restrict__ bias) {
    __shared__ float sW[RR * 6];
    __shared__ float sR[18], sB[6];
    __shared__ float sp[6];
    for (int i = threadIdx.x; i < RR * 6; i += blockDim.x) sW[i] = W[i];
    if (threadIdx.x < 18) sR[threadIdx.x] = root[threadIdx.x];
    if (threadIdx.x < 6) { sB[threadIdx.x] = bias[threadIdx.x]; sp[threadIdx.x] = 0.f; }
    __syncthreads();
    int gw = (blockIdx.x * blockDim.x + threadIdx.x) >> 5;
    int lane = threadIdx.x & 31;
    if (gw < NN) {
        int2 rg = g_range[gw];
        const int* cntRow = g_cnt + (size_t)gw * RR;
        float a0 = 0, a1 = 0, a2 = 0, a3 = 0, a4 = 0, a5 = 0;
        int e = rg.x + lane;
        for (; e + 32 < rg.y; e += 64) {
            int p0 = g_sorted[e];
            int p1 = g_sorted[e + 32];
            float4 x0 = __ldg(&g_h2[p0 >> 7]);
            float4 x1 = __ldg(&g_h2[p1 >> 7]);
            float iv0 = __fdividef(1.f, (float)cntRow[p0 & 127]);
            float iv1 = __fdividef(1.f, (float)cntRow[p1 & 127]);
            const float* w0 = sW + (p0 & 127) * 6;
            const float* w1 = sW + (p1 & 127) * 6;
            float t0 = x0.x * iv0, t1 = x0.y * iv0, t2 = x0.z * iv0;
            a0 += t0 * w0[0]; a1 += t0 * w0[1];
            a2 += t1 * w0[2]; a3 += t1 * w0[3];
            a4 += t2 * w0[4]; a5 += t2 * w0[5];
            float u0 = x1.x * iv1, u1 = x1.y * iv1, u2 = x1.z * iv1;
            a0 += u0 * w1[0]; a1 += u0 * w1[1];
            a2 += u1 * w1[2]; a3 += u1 * w1[3];
            a4 += u2 * w1[4]; a5 += u2 * w1[5];
        }
        if (e < rg.y) {
            int p0 = g_sorted[e];
            float4 x0 = __ldg(&g_h2[p0 >> 7]);
            float iv0 = __fdividef(1.f, (float)cntRow[p0 & 127]);
            const float* w0 = sW + (p0 & 127) * 6;
            float t0 = x0.x * iv0, t1 = x0.y * iv0, t2 = x0.z * iv0;
            a0 += t0 * w0[0]; a1 += t0 * w0[1];
            a2 += t1 * w0[2]; a3 += t1 * w0[3];
            a4 += t2 * w0[4]; a5 += t2 * w0[5];
        }
#pragma unroll
        for (int o = 16; o; o >>= 1) {
            a0 += __shfl_down_sync(0xffffffffu, a0, o);
            a1 += __shfl_down_sync(0xffffffffu, a1, o);
            a2 += __shfl_down_sync(0xffffffffu, a2, o);
            a3 += __shfl_down_sync(0xffffffffu, a3, o);
            a4 += __shfl_down_sync(0xffffffffu, a4, o);
            a5 += __shfl_down_sync(0xffffffffu, a5, o);
        }
        if (lane == 0) {
            float4 xv = g_h2[gw];
            float h[6] = {a0, a1, a2, a3, a4, a5};
#pragma unroll
            for (int j = 0; j < 6; j++) {
                float v = h[j] + xv.x * sR[j] + xv.y * sR[6 + j] + xv.z * sR[12 + j] + sB[j];
                h[j] = v > 0.f ? v : 0.f;
                atomicAdd(&sp[j], h[j]);
            }
        }
    }
    __syncthreads();
    if (threadIdx.x < 6) atomicAdd(&g_pool[threadIdx.x], sp[threadIdx.x]);
}

// ---------------- finalize: pooled mean + log_softmax ----------------
__global__ void finalize(float* __restrict__ out) {
    float v[6];
#pragma unroll
    for (int j = 0; j < 6; j++) v[j] = g_pool[j] / (float)NN;
    float m = v[0];
#pragma unroll
    for (int j = 1; j < 6; j++) m = fmaxf(m, v[j]);
    float s = 0.f;
#pragma unroll
    for (int j = 0; j < 6; j++) s += expf(v[j] - m);
    float l = logf(s);
#pragma unroll
    for (int j = 0; j < 6; j++) out[j] = v[j] - m - l;
}

extern "C" void kernel_launch(void* const* d_in, const int* in_sizes, int n_in,
                              void* d_out, int out_size) {
    const float* x     = (const float*)d_in[0];
    const int*   ei    = (const int*)d_in[1];
    const int*   src   = ei;
    const int*   dst   = ei + EE;
    const int*   et    = (const int*)d_in[3];
    const float* W1    = (const float*)d_in[4];
    const float* root1 = (const float*)d_in[5];
    const float* b1    = (const float*)d_in[6];
    const float* W2    = (const float*)d_in[7];
    const float* root2 = (const float*)d_in[8];
    const float* b2    = (const float*)d_in[9];
    const float* W3    = (const float*)d_in[10];
    const float* root3 = (const float*)d_in[11];
    const float* b3    = (const float*)d_in[12];
    float* out = (float*)d_out;

    const int LAYER_BLOCKS = (NN * 32 + 255) / 256;   // warp per node

    zero_pad<<<2048, 256>>>(x);                        // 1
    count_deg<<<2048, 256>>>(dst, et);                 // 2
    offsets_k<<<(NN + 255) / 256, 256>>>();            // 3
    scatter_k<<<2048, 256>>>(src, dst, et);            // 4  <- profiled slot
    layer1_k<<<LAYER_BLOCKS, 256>>>(W1, root1, b1);    // 5
    layer2_k<<<LAYER_BLOCKS, 256>>>(W2, root2, b2);    // 6
    layer3_k<<<LAYER_BLOCKS, 256>>>(W3, root3, b3);    // 7
    finalize<<<1, 1>>>(out);                           // 8
}

// round 8
// speedup vs baseline: 1.1388x; 1.1388x over previous
#include <cuda_runtime.h>
#include <math.h>
#include <stdint.h>

#define NN 100000
#define EE 6400000
#define RR 90

// ---------------- static device scratch (allocation-free rule) ----------------
__device__ int    g_cnt[(size_t)NN * RR];   // per-(dst,rel) edge counts (36 MB)
__device__ int2   g_range[NN];              // (beg, end) per node in g_sorted
__device__ int    g_cursor[NN];             // scatter cursors
__device__ int    g_total;                  // running offset counter
__device__ int    g_sorted[EE];             // dst-grouped packed (src<<7 | rel)
__device__ float4 g_x4[NN];                 // x padded to 4
__device__ float4 g_h1[(size_t)NN * 2];     // h1, stride 8 floats (6 used + 2 pad)
__device__ float4 g_h2[NN];                 // h2, stride 4 floats (3 used + 1 pad)
__device__ float  g_pool[8];

// ---------------- zero counts/pool/total + pad x ----------------
__global__ void zero_pad(const float* __restrict__ x) {
    int idx = blockIdx.x * blockDim.x + threadIdx.x;
    int stride = gridDim.x * blockDim.x;
    int4* c = (int4*)g_cnt;
    const int n4 = (NN * RR) / 4;
    for (int i = idx; i < n4; i += stride) c[i] = make_int4(0, 0, 0, 0);
    for (int i = idx; i < NN; i += stride)
        g_x4[i] = make_float4(x[i * 3], x[i * 3 + 1], x[i * 3 + 2], 0.f);
    if (idx < 8) g_pool[idx] = 0.f;
    if (idx == 0) g_total = 0;
}

// ---------------- count pass: cnt[dst*R+et]++ (8 edges/thread, RED only) ----------------
__global__ void count_k(const int* __restrict__ dst, const int* __restrict__ et) {
    const int4* d4 = (const int4*)dst;
    const int4* e4 = (const int4*)et;
    const int n8 = EE / 8;                      // 800,000
    int i = blockIdx.x * blockDim.x + threadIdx.x;
    if (i >= n8) return;
    int4 da = d4[2 * i], db = d4[2 * i + 1];
    int4 ea = e4[2 * i], eb = e4[2 * i + 1];
    atomicAdd(&g_cnt[da.x * RR + ea.x], 1);
    atomicAdd(&g_cnt[da.y * RR + ea.y], 1);
    atomicAdd(&g_cnt[da.z * RR + ea.z], 1);
    atomicAdd(&g_cnt[da.w * RR + ea.w], 1);
    atomicAdd(&g_cnt[db.x * RR + eb.x], 1);
    atomicAdd(&g_cnt[db.y * RR + eb.y], 1);
    atomicAdd(&g_cnt[db.z * RR + eb.z], 1);
    atomicAdd(&g_cnt[db.w * RR + eb.w], 1);
}

// ---------------- fused degree + offsets: 1024-thr block = 32 warps = 32 nodes ----------------
// Each warp row-sums its node's cnt row -> deg; warp 0 scans the 32 degrees and
// claims a contiguous range with ONE atomic per block (order across blocks is
// irrelevant: any disjoint range assignment works).
__global__ void __launch_bounds__(1024) degoff_k() {
    __shared__ int s_deg[32];
    int wid = threadIdx.x >> 5, lane = threadIdx.x & 31;
    int node0 = blockIdx.x * 32;
    int node = node0 + wid;
    size_t base = (size_t)node * RR;
    int s = g_cnt[base + lane];
    if (lane < RR - 32) s += g_cnt[base + 32 + lane];
    if (lane < RR - 64) s += g_cnt[base + 64 + lane];
#pragma unroll
    for (int o = 16; o; o >>= 1) s += __shfl_down_sync(0xffffffffu, s, o);
    if (lane == 0) s_deg[wid] = s;
    __syncthreads();
    if (wid == 0) {
        int d = s_deg[lane];
        int x = d;
#pragma unroll
        for (int o = 1; o < 32; o <<= 1) {
            int y = __shfl_up_sync(0xffffffffu, x, o);
            if (lane >= o) x += y;
        }
        int tot = __shfl_sync(0xffffffffu, x, 31);
        int bse = 0;
        if (lane == 31) bse = atomicAdd(&g_total, tot);
        bse = __shfl_sync(0xffffffffu, bse, 31);
        int beg = bse + x - d;
        g_range[node0 + lane] = make_int2(beg, beg + d);
        g_cursor[node0 + lane] = beg;
    }
}

// ---------------- counting-sort scatter: 8 independent atomic->store chains/thread ----------------
__global__ void scatter_k(const int* __restrict__ src, const int* __restrict__ dst,
                          const int* __restrict__ et) {
    const int4* s4 = (const int4*)src;
    const int4* d4 = (const int4*)dst;
    const int4* e4 = (const int4*)et;
    const int n8 = EE / 8;                      // 800,000
    int i = blockIdx.x * blockDim.x + threadIdx.x;
    if (i >= n8) return;
    int4 sa = s4[2 * i], sb = s4[2 * i + 1];
    int4 da = d4[2 * i], db = d4[2 * i + 1];
    int4 ta = e4[2 * i], tb = e4[2 * i + 1];
    int p0 = atomicAdd(&g_cursor[da.x], 1);
    int p1 = atomicAdd(&g_cursor[da.y], 1);
    int p2 = atomicAdd(&g_cursor[da.z], 1);
    int p3 = atomicAdd(&g_cursor[da.w], 1);
    int p4 = atomicAdd(&g_cursor[db.x], 1);
    int p5 = atomicAdd(&g_cursor[db.y], 1);
    int p6 = atomicAdd(&g_cursor[db.z], 1);
    int p7 = atomicAdd(&g_cursor[db.w], 1);
    g_sorted[p0] = (sa.x << 7) | ta.x;
    g_sorted[p1] = (sa.y << 7) | ta.y;
    g_sorted[p2] = (sa.z << 7) | ta.z;
    g_sorted[p3] = (sa.w << 7) | ta.w;
    g_sorted[p4] = (sb.x << 7) | tb.x;
    g_sorted[p5] = (sb.y << 7) | tb.y;
    g_sorted[p6] = (sb.z << 7) | tb.z;
    g_sorted[p7] = (sb.w << 7) | tb.w;
}

// ---------------- layer 1: mean aggr (3 -> 6) + root + relu, HALF-warp per node ----------------
__global__ void __launch_bounds__(256) layer1_k(const float* __restrict__ W,
                                                const float* __restrict__ root,
                                                const float* __restrict__ bias) {
    __shared__ float sW[RR * 6];
    __shared__ float sR[18], sB[6];
    for (int i = threadIdx.x; i < RR * 6; i += blockDim.x) sW[i] = W[i];
    if (threadIdx.x < 18) sR[threadIdx.x] = root[threadIdx.x];
    if (threadIdx.x < 6) sB[threadIdx.x] = bias[threadIdx.x];
    __syncthreads();
    int gw = (blockIdx.x * blockDim.x + threadIdx.x) >> 4;    // node (16 lanes/node)
    if (gw >= NN) return;
    int lane = threadIdx.x & 15;
    int2 rg = g_range[gw];
    const int* cntRow = g_cnt + (size_t)gw * RR;
    float a0 = 0, a1 = 0, a2 = 0, a3 = 0, a4 = 0, a5 = 0;
    int e = rg.x + lane;
    for (; e + 48 < rg.y; e += 64) {
        int p0 = g_sorted[e],      p1 = g_sorted[e + 16];
        int p2 = g_sorted[e + 32], p3 = g_sorted[e + 48];
        float4 x0 = __ldg(&g_x4[p0 >> 7]);
        float4 x1 = __ldg(&g_x4[p1 >> 7]);
        float4 x2 = __ldg(&g_x4[p2 >> 7]);
        float4 x3 = __ldg(&g_x4[p3 >> 7]);
        float iv0 = __fdividef(1.f, (float)cntRow[p0 & 127]);
        float iv1 = __fdividef(1.f, (float)cntRow[p1 & 127]);
        float iv2 = __fdividef(1.f, (float)cntRow[p2 & 127]);
        float iv3 = __fdividef(1.f, (float)cntRow[p3 & 127]);
        const float* w0 = sW + (p0 & 127) * 6;
        const float* w1 = sW + (p1 & 127) * 6;
        const float* w2 = sW + (p2 & 127) * 6;
        const float* w3 = sW + (p3 & 127) * 6;
        float t0, t1, t2;
        t0 = x0.x * iv0; t1 = x0.y * iv0; t2 = x0.z * iv0;
        a0 += t0 * w0[0]; a1 += t0 * w0[1]; a2 += t1 * w0[2];
        a3 += t1 * w0[3]; a4 += t2 * w0[4]; a5 += t2 * w0[5];
        t0 = x1.x * iv1; t1 = x1.y * iv1; t2 = x1.z * iv1;
        a0 += t0 * w1[0]; a1 += t0 * w1[1]; a2 += t1 * w1[2];
        a3 += t1 * w1[3]; a4 += t2 * w1[4]; a5 += t2 * w1[5];
        t0 = x2.x * iv2; t1 = x2.y * iv2; t2 = x2.z * iv2;
        a0 += t0 * w2[0]; a1 += t0 * w2[1]; a2 += t1 * w2[2];
        a3 += t1 * w2[3]; a4 += t2 * w2[4]; a5 += t2 * w2[5];
        t0 = x3.x * iv3; t1 = x3.y * iv3; t2 = x3.z * iv3;
        a0 += t0 * w3[0]; a1 += t0 * w3[1]; a2 += t1 * w3[2];
        a3 += t1 * w3[3]; a4 += t2 * w3[4]; a5 += t2 * w3[5];
    }
    for (; e < rg.y; e += 16) {
        int p0 = g_sorted[e];
        float4 x0 = __ldg(&g_x4[p0 >> 7]);
        float iv0 = __fdividef(1.f, (float)cntRow[p0 & 127]);
        const float* w0 = sW + (p0 & 127) * 6;
        float t0 = x0.x * iv0, t1 = x0.y * iv0, t2 = x0.z * iv0;
        a0 += t0 * w0[0]; a1 += t0 * w0[1]; a2 += t1 * w0[2];
        a3 += t1 * w0[3]; a4 += t2 * w0[4]; a5 += t2 * w0[5];
    }
#pragma unroll
    for (int o = 8; o; o >>= 1) {
        a0 += __shfl_down_sync(0xffffffffu, a0, o, 16);
        a1 += __shfl_down_sync(0xffffffffu, a1, o, 16);
        a2 += __shfl_down_sync(0xffffffffu, a2, o, 16);
        a3 += __shfl_down_sync(0xffffffffu, a3, o, 16);
        a4 += __shfl_down_sync(0xffffffffu, a4, o, 16);
        a5 += __shfl_down_sync(0xffffffffu, a5, o, 16);
    }
    if (lane == 0) {
        float4 xv = g_x4[gw];
        float h[6] = {a0, a1, a2, a3, a4, a5};
#pragma unroll
        for (int j = 0; j < 6; j++) {
            float v = h[j] + xv.x * sR[j] + xv.y * sR[6 + j] + xv.z * sR[12 + j] + sB[j];
            h[j] = v > 0.f ? v : 0.f;
        }
        g_h1[(size_t)gw * 2]     = make_float4(h[0], h[1], h[2], h[3]);
        g_h1[(size_t)gw * 2 + 1] = make_float4(h[4], h[5], 0.f, 0.f);
    }
}

// ---------------- layer 2: add aggr (6 -> 3) + root + relu, HALF-warp per node ----------------
__global__ void __launch_bounds__(256) layer2_k(const float* __restrict__ W,
                                                const float* __restrict__ root,
                                                const float* __restrict__ bias) {
    __shared__ float sW[RR * 6];
    __shared__ float sR[18], sB[3];
    for (int i = threadIdx.x; i < RR * 6; i += blockDim.x) sW[i] = W[i];
    if (threadIdx.x < 18) sR[threadIdx.x] = root[threadIdx.x];
    if (threadIdx.x < 3) sB[threadIdx.x] = bias[threadIdx.x];
    __syncthreads();
    int gw = (blockIdx.x * blockDim.x + threadIdx.x) >> 4;
    if (gw >= NN) return;
    int lane = threadIdx.x & 15;
    int2 rg = g_range[gw];
    float a0 = 0, a1 = 0, a2 = 0;
    int e = rg.x + lane;
    for (; e + 16 < rg.y; e += 32) {
        int p0 = g_sorted[e];
        int p1 = g_sorted[e + 16];
        int s0 = p0 >> 7, s1 = p1 >> 7;
        float4 ha0 = __ldg(&g_h1[(size_t)s0 * 2]);
        float4 hb0 = __ldg(&g_h1[(size_t)s0 * 2 + 1]);
        float4 ha1 = __ldg(&g_h1[(size_t)s1 * 2]);
        float4 hb1 = __ldg(&g_h1[(size_t)s1 * 2 + 1]);
        const float* w0 = sW + (p0 & 127) * 6;
        const float* w1 = sW + (p1 & 127) * 6;
        a0 += ha0.x * w0[0] + ha0.y * w0[1];
        a1 += ha0.z * w0[2] + ha0.w * w0[3];
        a2 += hb0.x * w0[4] + hb0.y * w0[5];
        a0 += ha1.x * w1[0] + ha1.y * w1[1];
        a1 += ha1.z * w1[2] + ha1.w * w1[3];
        a2 += hb1.x * w1[4] + hb1.y * w1[5];
    }
    if (e < rg.y) {
        int p0 = g_sorted[e];
        int s0 = p0 >> 7;
        float4 ha0 = __ldg(&g_h1[(size_t)s0 * 2]);
        float4 hb0 = __ldg(&g_h1[(size_t)s0 * 2 + 1]);
        const float* w0 = sW + (p0 & 127) * 6;
        a0 += ha0.x * w0[0] + ha0.y * w0[1];
        a1 += ha0.z * w0[2] + ha0.w * w0[3];
        a2 += hb0.x * w0[4] + hb0.y * w0[5];
    }
#pragma unroll
    for (int o = 8; o; o >>= 1) {
        a0 += __shfl_down_sync(0xffffffffu, a0, o, 16);
        a1 += __shfl_down_sync(0xffffffffu, a1, o, 16);
        a2 += __shfl_down_sync(0xffffffffu, a2, o, 16);
    }
    if (lane == 0) {
        float4 ha = g_h1[(size_t)gw * 2];
        float4 hb = g_h1[(size_t)gw * 2 + 1];
        float hin[6] = {ha.x, ha.y, ha.z, ha.w, hb.x, hb.y};
        float h[3] = {a0, a1, a2};
#pragma unroll
        for (int j = 0; j < 3; j++) {
            float v = h[j] + sB[j];
#pragma unroll
            for (int k = 0; k < 6; k++) v += hin[k] * sR[k * 3 + j];
            h[j] = v > 0.f ? v : 0.f;
        }
        g_h2[gw] = make_float4(h[0], h[1], h[2], 0.f);
    }
}

// ---------------- layer 3: mean aggr (3 -> 6) + root + relu + mean pool ----------------
__global__ void __launch_bounds__(256) layer3_k(const float* __restrict__ W,
                                                const float* __restrict__ root,
                                                const float* __restrict__ bias) {
    __shared__ float sW[RR * 6];
    __shared__ float sR[18], sB[6];
    __shared__ float sp[6];
    for (int i = threadIdx.x; i < RR * 6; i += blockDim.x) sW[i] = W[i];
    if (threadIdx.x < 18) sR[threadIdx.x] = root[threadIdx.x];
    if (threadIdx.x < 6) { sB[threadIdx.x] = bias[threadIdx.x]; sp[threadIdx.x] = 0.f; }
    __syncthreads();
    int gw = (blockIdx.x * blockDim.x + threadIdx.x) >> 4;
    int lane = threadIdx.x & 15;
    if (gw < NN) {
        int2 rg = g_range[gw];
        const int* cntRow = g_cnt + (size_t)gw * RR;
        float a0 = 0, a1 = 0, a2 = 0, a3 = 0, a4 = 0, a5 = 0;
        int e = rg.x + lane;
        for (; e + 48 < rg.y; e += 64) {
            int p0 = g_sorted[e],      p1 = g_sorted[e + 16];
            int p2 = g_sorted[e + 32], p3 = g_sorted[e + 48];
            float4 x0 = __ldg(&g_h2[p0 >> 7]);
            float4 x1 = __ldg(&g_h2[p1 >> 7]);
            float4 x2 = __ldg(&g_h2[p2 >> 7]);
            float4 x3 = __ldg(&g_h2[p3 >> 7]);
            float iv0 = __fdividef(1.f, (float)cntRow[p0 & 127]);
            float iv1 = __fdividef(1.f, (float)cntRow[p1 & 127]);
            float iv2 = __fdividef(1.f, (float)cntRow[p2 & 127]);
            float iv3 = __fdividef(1.f, (float)cntRow[p3 & 127]);
            const float* w0 = sW + (p0 & 127) * 6;
            const float* w1 = sW + (p1 & 127) * 6;
            const float* w2 = sW + (p2 & 127) * 6;
            const float* w3 = sW + (p3 & 127) * 6;
            float t0, t1, t2;
            t0 = x0.x * iv0; t1 = x0.y * iv0; t2 = x0.z * iv0;
            a0 += t0 * w0[0]; a1 += t0 * w0[1]; a2 += t1 * w0[2];
            a3 += t1 * w0[3]; a4 += t2 * w0[4]; a5 += t2 * w0[5];
            t0 = x1.x * iv1; t1 = x1.y * iv1; t2 = x1.z * iv1;
            a0 += t0 * w1[0]; a1 += t0 * w1[1]; a2 += t1 * w1[2];
            a3 += t1 * w1[3]; a4 += t2 * w1[4]; a5 += t2 * w1[5];
            t0 = x2.x * iv2; t1 = x2.y * iv2; t2 = x2.z * iv2;
            a0 += t0 * w2[0]; a1 += t0 * w2[1]; a2 += t1 * w2[2];
            a3 += t1 * w2[3]; a4 += t2 * w2[4]; a5 += t2 * w2[5];
            t0 = x3.x * iv3; t1 = x3.y * iv3; t2 = x3.z * iv3;
            a0 += t0 * w3[0]; a1 += t0 * w3[1]; a2 += t1 * w3[2];
            a3 += t1 * w3[3]; a4 += t2 * w3[4]; a5 += t2 * w3[5];
        }
        for (; e < rg.y; e += 16) {
            int p0 = g_sorted[e];
            float4 x0 = __ldg(&g_h2[p0 >> 7]);
            float iv0 = __fdividef(1.f, (float)cntRow[p0 & 127]);
            const float* w0 = sW + (p0 & 127) * 6;
            float t0 = x0.x * iv0, t1 = x0.y * iv0, t2 = x0.z * iv0;
            a0 += t0 * w0[0]; a1 += t0 * w0[1]; a2 += t1 * w0[2];
            a3 += t1 * w0[3]; a4 += t2 * w0[4]; a5 += t2 * w0[5];
        }
#pragma unroll
        for (int o = 8; o; o >>= 1) {
            a0 += __shfl_down_sync(0xffffffffu, a0, o, 16);
            a1 += __shfl_down_sync(0xffffffffu, a1, o, 16);
            a2 += __shfl_down_sync(0xffffffffu, a2, o, 16);
            a3 += __shfl_down_sync(0xffffffffu, a3, o, 16);
            a4 += __shfl_down_sync(0xffffffffu, a4, o, 16);
            a5 += __shfl_down_sync(0xffffffffu, a5, o, 16);
        }
        if (lane == 0) {
            float4 xv = g_h2[gw];
            float h[6] = {a0, a1, a2, a3, a4, a5};
#pragma unroll
            for (int j = 0; j < 6; j++) {
                float v = h[j] + xv.x * sR[j] + xv.y * sR[6 + j] + xv.z * sR[12 + j] + sB[j];
                h[j] = v > 0.f ? v : 0.f;
                atomicAdd(&sp[j], h[j]);
            }
        }
    }
    __syncthreads();
    if (threadIdx.x < 6) atomicAdd(&g_pool[threadIdx.x], sp[threadIdx.x]);
}

// ---------------- finalize: pooled mean + log_softmax ----------------
__global__ void finalize(float* __restrict__ out) {
    float v[6];
#pragma unroll
    for (int j = 0; j < 6; j++) v[j] = g_pool[j] / (float)NN;
    float m = v[0];
#pragma unroll
    for (int j = 1; j < 6; j++) m = fmaxf(m, v[j]);
    float s = 0.f;
#pragma unroll
    for (int j = 0; j < 6; j++) s += expf(v[j] - m);
    float l = logf(s);
#pragma unroll
    for (int j = 0; j < 6; j++) out[j] = v[j] - m - l;
}

extern "C" void kernel_launch(void* const* d_in, const int* in_sizes, int n_in,
                              void* d_out, int out_size) {
    const float* x     = (const float*)d_in[0];
    const int*   ei    = (const int*)d_in[1];
    const int*   src   = ei;
    const int*   dst   = ei + EE;
    const int*   et    = (const int*)d_in[3];
    const float* W1    = (const float*)d_in[4];
    const float* root1 = (const float*)d_in[5];
    const float* b1    = (const float*)d_in[6];
    const float* W2    = (const float*)d_in[7];
    const float* root2 = (const float*)d_in[8];
    const float* b2    = (const float*)d_in[9];
    const float* W3    = (const float*)d_in[10];
    const float* root3 = (const float*)d_in[11];
    const float* b3    = (const float*)d_in[12];
    float* out = (float*)d_out;

    const int LAYER_BLOCKS = (NN * 16 + 255) / 256;   // half-warp per node -> 6250
    const int EDGE8_BLOCKS = (EE / 8 + 255) / 256;    // 3125 (one iter/thread)

    zero_pad<<<2048, 256>>>(x);                        // 1
    count_k<<<EDGE8_BLOCKS, 256>>>(dst, et);           // 2
    degoff_k<<<NN / 32, 1024>>>();                     // 3
    scatter_k<<<EDGE8_BLOCKS, 256>>>(src, dst, et);    // 4  <- profiled slot
    layer1_k<<<LAYER_BLOCKS, 256>>>(W1, root1, b1);    // 5
    layer2_k<<<LAYER_BLOCKS, 256>>>(W2, root2, b2);    // 6
    layer3_k<<<LAYER_BLOCKS, 256>>>(W3, root3, b3);    // 7
    finalize<<<1, 1>>>(out);                           // 8
}

// round 9
// speedup vs baseline: 1.1399x; 1.0010x over previous
#include <cuda_runtime.h>
#include <math.h>
#include <stdint.h>

#define NN 100000
#define EE 6400000
#define RR 90

// ---------------- static device scratch (allocation-free rule) ----------------
__device__ int    g_cnt[(size_t)NN * RR];   // per-(dst,rel) edge counts (36 MB)
__device__ int    g_cell[(size_t)NN * RR];  // per-(dst,rel) start offset in g_sorted (36 MB)
__device__ int    g_rank[EE];               // per-edge rank within its (dst,rel) cell (25.6 MB)
__device__ int2   g_range[NN];              // (beg, end) per node in g_sorted
__device__ int    g_total;                  // running offset counter
__device__ int    g_sorted[EE];             // dst-grouped packed (src<<7 | rel)
__device__ float4 g_x4[NN];                 // x padded to 4
__device__ float4 g_h1[(size_t)NN * 2];     // h1, stride 8 floats (6 used + 2 pad)
__device__ float4 g_h2[NN];                 // h2, stride 4 floats (3 used + 1 pad)
__device__ float  g_pool[8];

// ---------------- zero counts/pool/total + pad x ----------------
__global__ void zero_pad(const float* __restrict__ x) {
    int idx = blockIdx.x * blockDim.x + threadIdx.x;
    int stride = gridDim.x * blockDim.x;
    int4* c = (int4*)g_cnt;
    const int n4 = (NN * RR) / 4;
    for (int i = idx; i < n4; i += stride) c[i] = make_int4(0, 0, 0, 0);
    for (int i = idx; i < NN; i += stride)
        g_x4[i] = make_float4(x[i * 3], x[i * 3 + 1], x[i * 3 + 2], 0.f);
    if (idx < 8) g_pool[idx] = 0.f;
    if (idx == 0) g_total = 0;
}

// ---------------- count pass: rank[e] = cnt[dst*R+et]++  (8 edges/thread) ----------------
__global__ void count_k(const int* __restrict__ dst, const int* __restrict__ et) {
    const int4* d4 = (const int4*)dst;
    const int4* e4 = (const int4*)et;
    int4* r4 = (int4*)g_rank;
    const int n8 = EE / 8;                      // 800,000
    int i = blockIdx.x * blockDim.x + threadIdx.x;
    if (i >= n8) return;
    int4 da = d4[2 * i], db = d4[2 * i + 1];
    int4 ea = e4[2 * i], eb = e4[2 * i + 1];
    int4 ra, rb;
    ra.x = atomicAdd(&g_cnt[da.x * RR + ea.x], 1);
    ra.y = atomicAdd(&g_cnt[da.y * RR + ea.y], 1);
    ra.z = atomicAdd(&g_cnt[da.z * RR + ea.z], 1);
    ra.w = atomicAdd(&g_cnt[da.w * RR + ea.w], 1);
    rb.x = atomicAdd(&g_cnt[db.x * RR + eb.x], 1);
    rb.y = atomicAdd(&g_cnt[db.y * RR + eb.y], 1);
    rb.z = atomicAdd(&g_cnt[db.z * RR + eb.z], 1);
    rb.w = atomicAdd(&g_cnt[db.w * RR + eb.w], 1);
    r4[2 * i]     = ra;
    r4[2 * i + 1] = rb;
}

// ---------------- fused degree + node ranges + per-cell offsets ----------------
// 1024-thr block = 32 warps = 32 nodes. Each warp scans its node's 90-entry cnt
// row (3 segments of 32/32/26), producing per-cell exclusive offsets; warp 0
// scans the 32 node degrees and claims a contiguous range with ONE atomic.
__global__ void __launch_bounds__(1024) degoff_k() {
    __shared__ int s_deg[32];
    __shared__ int s_base[32];
    int wid = threadIdx.x >> 5, lane = threadIdx.x & 31;
    int node0 = blockIdx.x * 32;
    int node = node0 + wid;
    size_t base = (size_t)node * RR;
    int v0 = g_cnt[base + lane];
    int v1 = (lane < RR - 32) ? g_cnt[base + 32 + lane] : 0;
    int v2 = (lane < RR - 64) ? g_cnt[base + 64 + lane] : 0;
    // inclusive scans within warp
    int s0 = v0, s1 = v1, s2 = v2;
#pragma unroll
    for (int o = 1; o < 32; o <<= 1) {
        int y0 = __shfl_up_sync(0xffffffffu, s0, o);
        int y1 = __shfl_up_sync(0xffffffffu, s1, o);
        int y2 = __shfl_up_sync(0xffffffffu, s2, o);
        if (lane >= o) { s0 += y0; s1 += y1; s2 += y2; }
    }
    int T0 = __shfl_sync(0xffffffffu, s0, 31);
    int T1 = __shfl_sync(0xffffffffu, s1, 31);
    int T2 = __shfl_sync(0xffffffffu, s2, 31);
    int deg = T0 + T1 + T2;
    if (lane == 0) s_deg[wid] = deg;
    __syncthreads();
    if (wid == 0) {
        int d = s_deg[lane];
        int x = d;
#pragma unroll
        for (int o = 1; o < 32; o <<= 1) {
            int y = __shfl_up_sync(0xffffffffu, x, o);
            if (lane >= o) x += y;
        }
        int tot = __shfl_sync(0xffffffffu, x, 31);
        int bse = 0;
        if (lane == 31) bse = atomicAdd(&g_total, tot);
        bse = __shfl_sync(0xffffffffu, bse, 31);
        int beg = bse + x - d;
        s_base[lane] = beg;
        g_range[node0 + lane] = make_int2(beg, beg + d);
    }
    __syncthreads();
    int nb = s_base[wid];
    g_cell[base + lane] = nb + s0 - v0;                    // cells [0,32)
    if (lane < RR - 32) g_cell[base + 32 + lane] = nb + T0 + s1 - v1;        // [32,64)
    if (lane < RR - 64) g_cell[base + 64 + lane] = nb + T0 + T1 + s2 - v2;   // [64,90)
}

// ---------------- scatter: pos = cell_start + rank (NO atomics) ----------------
__global__ void scatter_k(const int* __restrict__ src, const int* __restrict__ dst,
                          const int* __restrict__ et) {
    const int4* s4 = (const int4*)src;
    const int4* d4 = (const int4*)dst;
    const int4* e4 = (const int4*)et;
    const int4* r4 = (const int4*)g_rank;
    const int n8 = EE / 8;                      // 800,000
    int i = blockIdx.x * blockDim.x + threadIdx.x;
    if (i >= n8) return;
    int4 sa = s4[2 * i], sb = s4[2 * i + 1];
    int4 da = d4[2 * i], db = d4[2 * i + 1];
    int4 ta = e4[2 * i], tb = e4[2 * i + 1];
    int4 ra = r4[2 * i], rb = r4[2 * i + 1];
    int p0 = __ldg(&g_cell[da.x * RR + ta.x]) + ra.x;
    int p1 = __ldg(&g_cell[da.y * RR + ta.y]) + ra.y;
    int p2 = __ldg(&g_cell[da.z * RR + ta.z]) + ra.z;
    int p3 = __ldg(&g_cell[da.w * RR + ta.w]) + ra.w;
    int p4 = __ldg(&g_cell[db.x * RR + tb.x]) + rb.x;
    int p5 = __ldg(&g_cell[db.y * RR + tb.y]) + rb.y;
    int p6 = __ldg(&g_cell[db.z * RR + tb.z]) + rb.z;
    int p7 = __ldg(&g_cell[db.w * RR + tb.w]) + rb.w;
    g_sorted[p0] = (sa.x << 7) | ta.x;
    g_sorted[p1] = (sa.y << 7) | ta.y;
    g_sorted[p2] = (sa.z << 7) | ta.z;
    g_sorted[p3] = (sa.w << 7) | ta.w;
    g_sorted[p4] = (sb.x << 7) | tb.x;
    g_sorted[p5] = (sb.y << 7) | tb.y;
    g_sorted[p6] = (sb.z << 7) | tb.z;
    g_sorted[p7] = (sb.w << 7) | tb.w;
}

// ---------------- layer 1: mean aggr (3 -> 6) + root + relu, HALF-warp per node ----------------
__global__ void __launch_bounds__(256) layer1_k(const float* __restrict__ W,
                                                const float* __restrict__ root,
                                                const float* __restrict__ bias) {
    __shared__ float sW[RR * 6];
    __shared__ float sR[18], sB[6];
    for (int i = threadIdx.x; i < RR * 6; i += blockDim.x) sW[i] = W[i];
    if (threadIdx.x < 18) sR[threadIdx.x] = root[threadIdx.x];
    if (threadIdx.x < 6) sB[threadIdx.x] = bias[threadIdx.x];
    __syncthreads();
    int gw = (blockIdx.x * blockDim.x + threadIdx.x) >> 4;    // node (16 lanes/node)
    if (gw >= NN) return;
    int lane = threadIdx.x & 15;
    int2 rg = g_range[gw];
    const int* cntRow = g_cnt + (size_t)gw * RR;
    float a0 = 0, a1 = 0, a2 = 0, a3 = 0, a4 = 0, a5 = 0;
    int e = rg.x + lane;
    for (; e + 48 < rg.y; e += 64) {
        int p0 = g_sorted[e],      p1 = g_sorted[e + 16];
        int p2 = g_sorted[e + 32], p3 = g_sorted[e + 48];
        float4 x0 = __ldg(&g_x4[p0 >> 7]);
        float4 x1 = __ldg(&g_x4[p1 >> 7]);
        float4 x2 = __ldg(&g_x4[p2 >> 7]);
        float4 x3 = __ldg(&g_x4[p3 >> 7]);
        float iv0 = __fdividef(1.f, (float)cntRow[p0 & 127]);
        float iv1 = __fdividef(1.f, (float)cntRow[p1 & 127]);
        float iv2 = __fdividef(1.f, (float)cntRow[p2 & 127]);
        float iv3 = __fdividef(1.f, (float)cntRow[p3 & 127]);
        const float* w0 = sW + (p0 & 127) * 6;
        const float* w1 = sW + (p1 & 127) * 6;
        const float* w2 = sW + (p2 & 127) * 6;
        const float* w3 = sW + (p3 & 127) * 6;
        float t0, t1, t2;
        t0 = x0.x * iv0; t1 = x0.y * iv0; t2 = x0.z * iv0;
        a0 += t0 * w0[0]; a1 += t0 * w0[1]; a2 += t1 * w0[2];
        a3 += t1 * w0[3]; a4 += t2 * w0[4]; a5 += t2 * w0[5];
        t0 = x1.x * iv1; t1 = x1.y * iv1; t2 = x1.z * iv1;
        a0 += t0 * w1[0]; a1 += t0 * w1[1]; a2 += t1 * w1[2];
        a3 += t1 * w1[3]; a4 += t2 * w1[4]; a5 += t2 * w1[5];
        t0 = x2.x * iv2; t1 = x2.y * iv2; t2 = x2.z * iv2;
        a0 += t0 * w2[0]; a1 += t0 * w2[1]; a2 += t1 * w2[2];
        a3 += t1 * w2[3]; a4 += t2 * w2[4]; a5 += t2 * w2[5];
        t0 = x3.x * iv3; t1 = x3.y * iv3; t2 = x3.z * iv3;
        a0 += t0 * w3[0]; a1 += t0 * w3[1]; a2 += t1 * w3[2];
        a3 += t1 * w3[3]; a4 += t2 * w3[4]; a5 += t2 * w3[5];
    }
    for (; e < rg.y; e += 16) {
        int p0 = g_sorted[e];
        float4 x0 = __ldg(&g_x4[p0 >> 7]);
        float iv0 = __fdividef(1.f, (float)cntRow[p0 & 127]);
        const float* w0 = sW + (p0 & 127) * 6;
        float t0 = x0.x * iv0, t1 = x0.y * iv0, t2 = x0.z * iv0;
        a0 += t0 * w0[0]; a1 += t0 * w0[1]; a2 += t1 * w0[2];
        a3 += t1 * w0[3]; a4 += t2 * w0[4]; a5 += t2 * w0[5];
    }
#pragma unroll
    for (int o = 8; o; o >>= 1) {
        a0 += __shfl_down_sync(0xffffffffu, a0, o, 16);
        a1 += __shfl_down_sync(0xffffffffu, a1, o, 16);
        a2 += __shfl_down_sync(0xffffffffu, a2, o, 16);
        a3 += __shfl_down_sync(0xffffffffu, a3, o, 16);
        a4 += __shfl_down_sync(0xffffffffu, a4, o, 16);
        a5 += __shfl_down_sync(0xffffffffu, a5, o, 16);
    }
    if (lane == 0) {
        float4 xv = g_x4[gw];
        float h[6] = {a0, a1, a2, a3, a4, a5};
#pragma unroll
        for (int j = 0; j < 6; j++) {
            float v = h[j] + xv.x * sR[j] + xv.y * sR[6 + j] + xv.z * sR[12 + j] + sB[j];
            h[j] = v > 0.f ? v : 0.f;
        }
        g_h1[(size_t)gw * 2]     = make_float4(h[0], h[1], h[2], h[3]);
        g_h1[(size_t)gw * 2 + 1] = make_float4(h[4], h[5], 0.f, 0.f);
    }
}

// ---------------- layer 2: add aggr (6 -> 3) + root + relu, HALF-warp per node ----------------
__global__ void __launch_bounds__(256) layer2_k(const float* __restrict__ W,
                                                const float* __restrict__ root,
                                                const float* __restrict__ bias) {
    __shared__ float sW[RR * 6];
    __shared__ float sR[18], sB[3];
    for (int i = threadIdx.x; i < RR * 6; i += blockDim.x) sW[i] = W[i];
    if (threadIdx.x < 18) sR[threadIdx.x] = root[threadIdx.x];
    if (threadIdx.x < 3) sB[threadIdx.x] = bias[threadIdx.x];
    __syncthreads();
    int gw = (blockIdx.x * blockDim.x + threadIdx.x) >> 4;
    if (gw >= NN) return;
    int lane = threadIdx.x & 15;
    int2 rg = g_range[gw];
    float a0 = 0, a1 = 0, a2 = 0;
    int e = rg.x + lane;
    for (; e + 16 < rg.y; e += 32) {
        int p0 = g_sorted[e];
        int p1 = g_sorted[e + 16];
        int s0 = p0 >> 7, s1 = p1 >> 7;
        float4 ha0 = __ldg(&g_h1[(size_t)s0 * 2]);
        float4 hb0 = __ldg(&g_h1[(size_t)s0 * 2 + 1]);
        float4 ha1 = __ldg(&g_h1[(size_t)s1 * 2]);
        float4 hb1 = __ldg(&g_h1[(size_t)s1 * 2 + 1]);
        const float* w0 = sW + (p0 & 127) * 6;
        const float* w1 = sW + (p1 & 127) * 6;
        a0 += ha0.x * w0[0] + ha0.y * w0[1];
        a1 += ha0.z * w0[2] + ha0.w * w0[3];
        a2 += hb0.x * w0[4] + hb0.y * w0[5];
        a0 += ha1.x * w1[0] + ha1.y * w1[1];
        a1 += ha1.z * w1[2] + ha1.w * w1[3];
        a2 += hb1.x * w1[4] + hb1.y * w1[5];
    }
    if (e < rg.y) {
        int p0 = g_sorted[e];
        int s0 = p0 >> 7;
        float4 ha0 = __ldg(&g_h1[(size_t)s0 * 2]);
        float4 hb0 = __ldg(&g_h1[(size_t)s0 * 2 + 1]);
        const float* w0 = sW + (p0 & 127) * 6;
        a0 += ha0.x * w0[0] + ha0.y * w0[1];
        a1 += ha0.z * w0[2] + ha0.w * w0[3];
        a2 += hb0.x * w0[4] + hb0.y * w0[5];
    }
#pragma unroll
    for (int o = 8; o; o >>= 1) {
        a0 += __shfl_down_sync(0xffffffffu, a0, o, 16);
        a1 += __shfl_down_sync(0xffffffffu, a1, o, 16);
        a2 += __shfl_down_sync(0xffffffffu, a2, o, 16);
    }
    if (lane == 0) {
        float4 ha = g_h1[(size_t)gw * 2];
        float4 hb = g_h1[(size_t)gw * 2 + 1];
        float hin[6] = {ha.x, ha.y, ha.z, ha.w, hb.x, hb.y};
        float h[3] = {a0, a1, a2};
#pragma unroll
        for (int j = 0; j < 3; j++) {
            float v = h[j] + sB[j];
#pragma unroll
            for (int k = 0; k < 6; k++) v += hin[k] * sR[k * 3 + j];
            h[j] = v > 0.f ? v : 0.f;
        }
        g_h2[gw] = make_float4(h[0], h[1], h[2], 0.f);
    }
}

// ---------------- layer 3: mean aggr (3 -> 6) + root + relu + mean pool ----------------
__global__ void __launch_bounds__(256) layer3_k(const float* __restrict__ W,
                                                const float* __restrict__ root,
                                                const float* __restrict__ bias) {
    __shared__ float sW[RR * 6];
    __shared__ float sR[18], sB[6];
    __shared__ float sp[6];
    for (int i = threadIdx.x; i < RR * 6; i += blockDim.x) sW[i] = W[i];
    if (threadIdx.x < 18) sR[threadIdx.x] = root[threadIdx.x];
    if (threadIdx.x < 6) { sB[threadIdx.x] = bias[threadIdx.x]; sp[threadIdx.x] = 0.f; }
    __syncthreads();
    int gw = (blockIdx.x * blockDim.x + threadIdx.x) >> 4;
    int lane = threadIdx.x & 15;
    if (gw < NN) {
        int2 rg = g_range[gw];
        const int* cntRow = g_cnt + (size_t)gw * RR;
        float a0 = 0, a1 = 0, a2 = 0, a3 = 0, a4 = 0, a5 = 0;
        int e = rg.x + lane;
        for (; e + 48 < rg.y; e += 64) {
            int p0 = g_sorted[e],      p1 = g_sorted[e + 16];
            int p2 = g_sorted[e + 32], p3 = g_sorted[e + 48];
            float4 x0 = __ldg(&g_h2[p0 >> 7]);
            float4 x1 = __ldg(&g_h2[p1 >> 7]);
            float4 x2 = __ldg(&g_h2[p2 >> 7]);
            float4 x3 = __ldg(&g_h2[p3 >> 7]);
            float iv0 = __fdividef(1.f, (float)cntRow[p0 & 127]);
            float iv1 = __fdividef(1.f, (float)cntRow[p1 & 127]);
            float iv2 = __fdividef(1.f, (float)cntRow[p2 & 127]);
            float iv3 = __fdividef(1.f, (float)cntRow[p3 & 127]);
            const float* w0 = sW + (p0 & 127) * 6;
            const float* w1 = sW + (p1 & 127) * 6;
            const float* w2 = sW + (p2 & 127) * 6;
            const float* w3 = sW + (p3 & 127) * 6;
            float t0, t1, t2;
            t0 = x0.x * iv0; t1 = x0.y * iv0; t2 = x0.z * iv0;
            a0 += t0 * w0[0]; a1 += t0 * w0[1]; a2 += t1 * w0[2];
            a3 += t1 * w0[3]; a4 += t2 * w0[4]; a5 += t2 * w0[5];
            t0 = x1.x * iv1; t1 = x1.y * iv1; t2 = x1.z * iv1;
            a0 += t0 * w1[0]; a1 += t0 * w1[1]; a2 += t1 * w1[2];
            a3 += t1 * w1[3]; a4 += t2 * w1[4]; a5 += t2 * w1[5];
            t0 = x2.x * iv2; t1 = x2.y * iv2; t2 = x2.z * iv2;
            a0 += t0 * w2[0]; a1 += t0 * w2[1]; a2 += t1 * w2[2];
            a3 += t1 * w2[3]; a4 += t2 * w2[4]; a5 += t2 * w2[5];
            t0 = x3.x * iv3; t1 = x3.y * iv3; t2 = x3.z * iv3;
            a0 += t0 * w3[0]; a1 += t0 * w3[1]; a2 += t1 * w3[2];
            a3 += t1 * w3[3]; a4 += t2 * w3[4]; a5 += t2 * w3[5];
        }
        for (; e < rg.y; e += 16) {
            int p0 = g_sorted[e];
            float4 x0 = __ldg(&g_h2[p0 >> 7]);
            float iv0 = __fdividef(1.f, (float)cntRow[p0 & 127]);
            const float* w0 = sW + (p0 & 127) * 6;
            float t0 = x0.x * iv0, t1 = x0.y * iv0, t2 = x0.z * iv0;
            a0 += t0 * w0[0]; a1 += t0 * w0[1]; a2 += t1 * w0[2];
            a3 += t1 * w0[3]; a4 += t2 * w0[4]; a5 += t2 * w0[5];
        }
#pragma unroll
        for (int o = 8; o; o >>= 1) {
            a0 += __shfl_down_sync(0xffffffffu, a0, o, 16);
            a1 += __shfl_down_sync(0xffffffffu, a1, o, 16);
            a2 += __shfl_down_sync(0xffffffffu, a2, o, 16);
            a3 += __shfl_down_sync(0xffffffffu, a3, o, 16);
            a4 += __shfl_down_sync(0xffffffffu, a4, o, 16);
            a5 += __shfl_down_sync(0xffffffffu, a5, o, 16);
        }
        if (lane == 0) {
            float4 xv = g_h2[gw];
            float h[6] = {a0, a1, a2, a3, a4, a5};
#pragma unroll
            for (int j = 0; j < 6; j++) {
                float v = h[j] + xv.x * sR[j] + xv.y * sR[6 + j] + xv.z * sR[12 + j] + sB[j];
                h[j] = v > 0.f ? v : 0.f;
                atomicAdd(&sp[j], h[j]);
            }
        }
    }
    __syncthreads();
    if (threadIdx.x < 6) atomicAdd(&g_pool[threadIdx.x], sp[threadIdx.x]);
}

// ---------------- finalize: pooled mean + log_softmax ----------------
__global__ void finalize(float* __restrict__ out) {
    float v[6];
#pragma unroll
    for (int j = 0; j < 6; j++) v[j] = g_pool[j] / (float)NN;
    float m = v[0];
#pragma unroll
    for (int j = 1; j < 6; j++) m = fmaxf(m, v[j]);
    float s = 0.f;
#pragma unroll
    for (int j = 0; j < 6; j++) s += expf(v[j] - m);
    float l = logf(s);
#pragma unroll
    for (int j = 0; j < 6; j++) out[j] = v[j] - m - l;
}

extern "C" void kernel_launch(void* const* d_in, const int* in_sizes, int n_in,
                              void* d_out, int out_size) {
    const float* x     = (const float*)d_in[0];
    const int*   ei    = (const int*)d_in[1];
    const int*   src   = ei;
    const int*   dst   = ei + EE;
    const int*   et    = (const int*)d_in[3];
    const float* W1    = (const float*)d_in[4];
    const float* root1 = (const float*)d_in[5];
    const float* b1    = (const float*)d_in[6];
    const float* W2    = (const float*)d_in[7];
    const float* root2 = (const float*)d_in[8];
    const float* b2    = (const float*)d_in[9];
    const float* W3    = (const float*)d_in[10];
    const float* root3 = (const float*)d_in[11];
    const float* b3    = (const float*)d_in[12];
    float* out = (float*)d_out;

    const int LAYER_BLOCKS = (NN * 16 + 255) / 256;   // half-warp per node -> 6250
    const int EDGE8_BLOCKS = (EE / 8 + 255) / 256;    // 3125 (one iter/thread)

    zero_pad<<<2048, 256>>>(x);                        // 1
    count_k<<<EDGE8_BLOCKS, 256>>>(dst, et);           // 2
    degoff_k<<<NN / 32, 1024>>>();                     // 3
    scatter_k<<<EDGE8_BLOCKS, 256>>>(src, dst, et);    // 4  <- profiled slot
    layer1_k<<<LAYER_BLOCKS, 256>>>(W1, root1, b1);    // 5
    layer2_k<<<LAYER_BLOCKS, 256>>>(W2, root2, b2);    // 6
    layer3_k<<<LAYER_BLOCKS, 256>>>(W3, root3, b3);    // 7
    finalize<<<1, 1>>>(out);                           // 8
}